// round 8
// baseline (speedup 1.0000x reference)
#include <cuda_runtime.h>
#include <cuda_fp16.h>
#include <cuda_bf16.h>

// GAT encoder. Structural constants: EMB=32, H=4, C=32 -> HC=128.
// Runtime shapes: GN=|x|, E=|adj|/2, N=|emb_table|/32, G=GN/N.

#define HC 128
#define EMB 32
#define MAX_N   8192
#define MAXDEG  96      // fixed-stride edge buckets per dst (deg~Poisson(16))

// Per-TOKEN tables (hl depends only on token id):
__device__ float g_HL[(size_t)MAX_N * HC];    // [N,128] fp32 (~1MB for N=2000)
__device__ float g_AS[MAX_N * 4];             // per-token src logits
__device__ float g_AD[MAX_N * 4];             // per-token dst logits
__device__ int   g_deg[MAX_N];                // zero at entry; last k_agg block re-zeroes
__device__ int   g_col[MAX_N * MAXDEG];       // bucketed src lists (no self loops)
__device__ int   g_done;                      // ticket for last-block reset

// packed f32x2 helpers (sm_103a; ptxas never emits FFMA2 from C++)
#define FMA_F32X2(d, a, b, c) \
    asm("fma.rn.f32x2 %0, %1, %2, %3;" : "=l"(d) : "l"(a), "l"(b), "l"(c))
#define PACK_F32X2(out, lo, hi) \
    asm("mov.b64 %0, {%1, %2};" : "=l"(out) : "f"(lo), "f"(hi))
#define UNPACK_F32X2(lo, hi, in) \
    asm("mov.b64 {%0, %1}, %2;" : "=f"(lo), "=f"(hi) : "l"(in))

// ---------------- launch 0: fused edge-bucket scatter + per-token features ----
#define TKB 128   // token blocks (256 thr = 8 warps each)

__global__ __launch_bounds__(256) void k_fused(const int* __restrict__ adj, int E,
                                               const float* __restrict__ emb,
                                               const float* __restrict__ lin_w,
                                               const float* __restrict__ att_src,
                                               const float* __restrict__ att_dst,
                                               int N, int SCB) {
    if ((int)blockIdx.x < SCB) {
        int e = blockIdx.x * 256 + threadIdx.x;
        if (e < E) {
            int s = adj[e];
            int d = adj[E + e];
            int pos = atomicAdd(&g_deg[d], 1);
            if (pos < MAXDEG) g_col[d * MAXDEG + pos] = s;
        }
        return;
    }
    // token part: warp per (token, head)
    int bi = (int)blockIdx.x - SCB;
    int w = threadIdx.x >> 5, lane = threadIdx.x & 31;
    int wg = bi * 8 + w;
    int head = wg & 3;
    int tok0 = wg >> 2;
    int tstride = TKB * 2;

    float wreg[EMB];
    int colidx = head * 32 + lane;
    #pragma unroll
    for (int k = 0; k < EMB; k++) wreg[k] = __ldg(&lin_w[k * HC + colidx]);
    float as_t = __ldg(&att_src[colidx]);
    float ad_t = __ldg(&att_dst[colidx]);

    for (int tok = tok0; tok < N; tok += tstride) {
        float ev = __ldg(&emb[(size_t)tok * EMB + lane]);
        float acc = 0.f;
        #pragma unroll
        for (int k = 0; k < EMB; k++)
            acc = fmaf(__shfl_sync(0xffffffffu, ev, k), wreg[k], acc);
        g_HL[(size_t)tok * HC + colidx] = acc;
        float ps = acc * as_t, pd = acc * ad_t;
        #pragma unroll
        for (int o = 16; o > 0; o >>= 1) {
            ps += __shfl_down_sync(0xffffffffu, ps, o);
            pd += __shfl_down_sync(0xffffffffu, pd, o);
        }
        if (lane == 0) {
            g_AS[tok * 4 + head] = ps;
            g_AD[tok * 4 + head] = pd;
        }
    }
}

// ---------------- launch 1: aggregation, warp per (g,dst) row ----------------
// Lane owns 4 consecutive output columns; head h = lane>>3.
// Per-(edge,head) smem entry: {alpha packed as f32x2, tok} (16B) -> one LDS.128.
// Payload: one LDG.128 (float4 == two f32x2 pairs) + 2 FFMA2 per edge.

#define WPB 8      // warps (rows) per block
#define CAP 48     // edges cached in smem per warp

__global__ __launch_bounds__(WPB * 32) void k_agg(const int* __restrict__ x,
                                                  const float* __restrict__ bias,
                                                  float* __restrict__ out,
                                                  int N, int G) {
    __shared__ ulonglong2 s_ent[WPB][CAP * 4];   // 24KB
    __shared__ int s_last;

    int w = threadIdx.x >> 5, lane = threadIdx.x & 31;
    int row = blockIdx.x * WPB + w;
    int g = row / N, n = row - g * N;
    bool active = (row < G * N);

    if (active) {
        const int* xg = x + (size_t)g * N;

        int deg = g_deg[n];
        if (deg > MAXDEG) deg = MAXDEG;
        int rs = n * MAXDEG;
        int h = lane >> 3;

        int dtok = __ldg(&xg[n]);
        float4 ad  = *(const float4*)&g_AD[dtok * 4];
        float4 asd = *(const float4*)&g_AS[dtok * 4];

        // self-loop exp term
        float4 eself;
        {
            float vx = asd.x + ad.x, vy = asd.y + ad.y, vz = asd.z + ad.z, vw = asd.w + ad.w;
            vx = vx > 0.f ? vx : 0.2f * vx;
            vy = vy > 0.f ? vy : 0.2f * vy;
            vz = vz > 0.f ? vz : 0.2f * vz;
            vw = vw > 0.f ? vw : 0.2f * vw;
            eself = make_float4(__expf(vx), __expf(vy), __expf(vz), __expf(vw));
        }

        // phase 1: per-edge exp(leaky_relu(logit)) -> smem entries; partial sums
        float4 sum = make_float4(0.f, 0.f, 0.f, 0.f);
        if (lane == 0) sum = eself;
        int nch = (deg + 31) >> 5;
        for (int c = 0; c < nch; c++) {
            int i = c * 32 + lane;
            if (i < deg) {
                int tok = __ldg(&xg[g_col[rs + i]]);
                float4 as = *(const float4*)&g_AS[tok * 4];
                float vx = as.x + ad.x, vy = as.y + ad.y, vz = as.z + ad.z, vw = as.w + ad.w;
                vx = vx > 0.f ? vx : 0.2f * vx;
                vy = vy > 0.f ? vy : 0.2f * vy;
                vz = vz > 0.f ? vz : 0.2f * vz;
                vw = vw > 0.f ? vw : 0.2f * vw;
                float ex = __expf(vx), ey = __expf(vy), ez = __expf(vz), ew = __expf(vw);
                sum.x += ex; sum.y += ey; sum.z += ez; sum.w += ew;
                if (i < CAP) {
                    unsigned long long tk = (unsigned long long)(unsigned)tok;
                    unsigned long long a0, a1, a2, a3;
                    PACK_F32X2(a0, ex, ex);
                    PACK_F32X2(a1, ey, ey);
                    PACK_F32X2(a2, ez, ez);
                    PACK_F32X2(a3, ew, ew);
                    s_ent[w][i * 4 + 0] = make_ulonglong2(a0, tk);
                    s_ent[w][i * 4 + 1] = make_ulonglong2(a1, tk);
                    s_ent[w][i * 4 + 2] = make_ulonglong2(a2, tk);
                    s_ent[w][i * 4 + 3] = make_ulonglong2(a3, tk);
                }
            }
        }
        __syncwarp();

        // softmax denominator reduction (per head)
        #pragma unroll
        for (int o = 16; o > 0; o >>= 1) {
            sum.x += __shfl_xor_sync(0xffffffffu, sum.x, o);
            sum.y += __shfl_xor_sync(0xffffffffu, sum.y, o);
            sum.z += __shfl_xor_sync(0xffffffffu, sum.z, o);
            sum.w += __shfl_xor_sync(0xffffffffu, sum.w, o);
        }
        float den = (h == 0) ? sum.x : (h == 1) ? sum.y : (h == 2) ? sum.z : sum.w;
        float inv = 1.f / den;

        // phase 2: gather fp32 HL rows, FFMA2 accumulate (unnormalized)
        const ulonglong2* HL2 = (const ulonglong2*)g_HL;   // lane owns 16B of row
        unsigned long long acc01 = 0ull, acc23 = 0ull;      // packed {0,0}
        {
            float alself = (h == 0) ? eself.x : (h == 1) ? eself.y
                         : (h == 2) ? eself.z : eself.w;
            unsigned long long a2;
            PACK_F32X2(a2, alself, alself);
            ulonglong2 hv = __ldg(&HL2[(size_t)dtok * 32 + lane]);
            FMA_F32X2(acc01, a2, hv.x, acc01);
            FMA_F32X2(acc23, a2, hv.y, acc23);
        }
        int cached = deg < CAP ? deg : CAP;
        const ulonglong2* pent = &s_ent[w][h];
        int e = 0;
        for (; e + 3 < cached; e += 4) {
            ulonglong2 t0 = pent[(e + 0) * 4];
            ulonglong2 t1 = pent[(e + 1) * 4];
            ulonglong2 t2 = pent[(e + 2) * 4];
            ulonglong2 t3 = pent[(e + 3) * 4];
            ulonglong2 v0 = __ldg(&HL2[(size_t)t0.y * 32 + lane]);
            ulonglong2 v1 = __ldg(&HL2[(size_t)t1.y * 32 + lane]);
            ulonglong2 v2 = __ldg(&HL2[(size_t)t2.y * 32 + lane]);
            ulonglong2 v3 = __ldg(&HL2[(size_t)t3.y * 32 + lane]);
            FMA_F32X2(acc01, t0.x, v0.x, acc01); FMA_F32X2(acc23, t0.x, v0.y, acc23);
            FMA_F32X2(acc01, t1.x, v1.x, acc01); FMA_F32X2(acc23, t1.x, v1.y, acc23);
            FMA_F32X2(acc01, t2.x, v2.x, acc01); FMA_F32X2(acc23, t2.x, v2.y, acc23);
            FMA_F32X2(acc01, t3.x, v3.x, acc01); FMA_F32X2(acc23, t3.x, v3.y, acc23);
        }
        for (; e < cached; e++) {
            ulonglong2 t0 = pent[e * 4];
            ulonglong2 v0 = __ldg(&HL2[(size_t)t0.y * 32 + lane]);
            FMA_F32X2(acc01, t0.x, v0.x, acc01);
            FMA_F32X2(acc23, t0.x, v0.y, acc23);
        }
        if (deg > CAP) {   // rare overflow path
            float adh = (h == 0) ? ad.x : (h == 1) ? ad.y : (h == 2) ? ad.z : ad.w;
            for (e = cached; e < deg; e++) {
                int tok = __ldg(&xg[g_col[rs + e]]);
                float v = g_AS[tok * 4 + h] + adh;
                v = v > 0.f ? v : 0.2f * v;
                float al = __expf(v);
                unsigned long long a2;
                PACK_F32X2(a2, al, al);
                ulonglong2 hv = __ldg(&HL2[(size_t)tok * 32 + lane]);
                FMA_F32X2(acc01, a2, hv.x, acc01);
                FMA_F32X2(acc23, a2, hv.y, acc23);
            }
        }

        float ax, ay, az, aw;
        UNPACK_F32X2(ax, ay, acc01);
        UNPACK_F32X2(az, aw, acc23);

        const float4* b4 = (const float4*)bias;
        float4 bb = __ldg(&b4[lane]);
        float4 o4;
        o4.x = ax * inv + bb.x;
        o4.y = ay * inv + bb.y;
        o4.z = az * inv + bb.z;
        o4.w = aw * inv + bb.w;
        ((float4*)out)[(size_t)row * 32 + lane] = o4;
    }

    // last-finishing block resets g_deg for the next graph replay
    __syncthreads();
    if (threadIdx.x == 0) {
        __threadfence();
        s_last = (atomicAdd(&g_done, 1) == (int)gridDim.x - 1);
    }
    __syncthreads();
    if (s_last) {
        for (int i = threadIdx.x; i < N; i += blockDim.x) g_deg[i] = 0;
        if (threadIdx.x == 0) g_done = 0;
    }
}

// ---------------- launch ----------------

extern "C" void kernel_launch(void* const* d_in, const int* in_sizes, int n_in,
                              void* d_out, int out_size) {
    const int*   x       = (const int*)  d_in[0];   // [G*N]
    const int*   adj     = (const int*)  d_in[1];   // [2,E]
    const float* emb     = (const float*)d_in[2];   // [N,32]
    const float* lin_w   = (const float*)d_in[3];   // [32,128]
    const float* att_src = (const float*)d_in[4];   // [128]
    const float* att_dst = (const float*)d_in[5];   // [128]
    const float* bias    = (const float*)d_in[6];   // [128]
    float* out = (float*)d_out;

    int GN = in_sizes[0];
    int E  = in_sizes[1] / 2;
    int N  = in_sizes[2] / EMB;
    int G  = GN / N;

    int SCB = (E + 255) / 256;
    k_fused<<<SCB + TKB, 256>>>(adj, E, emb, lin_w, att_src, att_dst, N, SCB);
    k_agg<<<(GN + WPB - 1) / WPB, WPB * 32>>>(x, bias, out, N, G);
    (void)n_in; (void)out_size;
}

// round 12
// speedup vs baseline: 1.4546x; 1.4546x over previous
#include <cuda_runtime.h>
#include <cuda_fp16.h>
#include <cuda_bf16.h>

// GAT encoder. Structural constants: EMB=32, H=4, C=32 -> HC=128.
// Runtime shapes: GN=|x|, E=|adj|/2, N=|emb_table|/32, G=GN/N.

#define HC 128
#define EMB 32
#define MAX_N   8192
#define MAXDEG  96      // fixed-stride edge buckets per dst (deg~Poisson(16))

// Per-TOKEN tables (hl depends only on token id):
__device__ __half g_HLh[(size_t)MAX_N * HC];   // [N,128] fp16 (~512KB for N=2000)
__device__ float  g_AS[MAX_N * 4];             // per-token src logits (fp32)
__device__ float  g_AD[MAX_N * 4];             // per-token dst logits (fp32)
__device__ int    g_deg[MAX_N];                // zero at entry; last k_agg block re-zeroes
__device__ int    g_col[MAX_N * MAXDEG];       // bucketed src lists (no self loops)
__device__ int    g_done;                      // ticket for last-block reset

// ---------------- launch 0: fused edge-bucket scatter + per-token features ----
#define TKB 128   // token blocks (256 thr = 8 warps each)

__global__ __launch_bounds__(256) void k_fused(const int* __restrict__ adj, int E,
                                               const float* __restrict__ emb,
                                               const float* __restrict__ lin_w,
                                               const float* __restrict__ att_src,
                                               const float* __restrict__ att_dst,
                                               int N, int SCB) {
    if ((int)blockIdx.x < SCB) {
        int e = blockIdx.x * 256 + threadIdx.x;
        if (e < E) {
            int s = adj[e];
            int d = adj[E + e];
            int pos = atomicAdd(&g_deg[d], 1);
            if (pos < MAXDEG) g_col[d * MAXDEG + pos] = s;
        }
        return;
    }
    // token part: warp per (token, head)
    int bi = (int)blockIdx.x - SCB;
    int w = threadIdx.x >> 5, lane = threadIdx.x & 31;
    int wg = bi * 8 + w;
    int head = wg & 3;
    int tok0 = wg >> 2;
    int tstride = TKB * 2;

    float wreg[EMB];
    int colidx = head * 32 + lane;
    #pragma unroll
    for (int k = 0; k < EMB; k++) wreg[k] = __ldg(&lin_w[k * HC + colidx]);
    float as_t = __ldg(&att_src[colidx]);
    float ad_t = __ldg(&att_dst[colidx]);

    for (int tok = tok0; tok < N; tok += tstride) {
        float ev = __ldg(&emb[(size_t)tok * EMB + lane]);
        float acc = 0.f;
        #pragma unroll
        for (int k = 0; k < EMB; k++)
            acc = fmaf(__shfl_sync(0xffffffffu, ev, k), wreg[k], acc);
        g_HLh[(size_t)tok * HC + colidx] = __float2half_rn(acc);
        float ps = acc * as_t, pd = acc * ad_t;      // logits fp32-exact
        #pragma unroll
        for (int o = 16; o > 0; o >>= 1) {
            ps += __shfl_down_sync(0xffffffffu, ps, o);
            pd += __shfl_down_sync(0xffffffffu, pd, o);
        }
        if (lane == 0) {
            g_AS[tok * 4 + head] = ps;
            g_AD[tok * 4 + head] = pd;
        }
    }
}

// ---------------- launch 1: aggregation, warp per (g,dst) row ----------------
// Lane owns 4 consecutive output columns; head h = lane>>3.
// Smem entry per (edge,head): float2{alpha_h, tok_as_float_bits} -> one LDS.64.

#define WPB 8      // warps (rows) per block
#define CAP 48     // edges cached in smem per warp

__device__ __forceinline__ float4 h4_to_f4(uint2 u) {
    float2 fa = __half22float2(*(__half2*)&u.x);
    float2 fb = __half22float2(*(__half2*)&u.y);
    return make_float4(fa.x, fa.y, fb.x, fb.y);
}

__global__ __launch_bounds__(WPB * 32) void k_agg(const int* __restrict__ x,
                                                  const float* __restrict__ bias,
                                                  float* __restrict__ out,
                                                  int N, int G) {
    __shared__ float2 s_ent[WPB][CAP * 4];   // {alpha_h, tok bits}: 12KB
    __shared__ int s_last;

    int w = threadIdx.x >> 5, lane = threadIdx.x & 31;
    int row = blockIdx.x * WPB + w;
    int g = row / N, n = row - g * N;
    bool active = (row < G * N);

    if (active) {
        const int* xg = x + (size_t)g * N;

        int deg = g_deg[n];
        if (deg > MAXDEG) deg = MAXDEG;
        int rs = n * MAXDEG;
        int h = lane >> 3;

        int dtok = __ldg(&xg[n]);
        float4 ad  = *(const float4*)&g_AD[dtok * 4];
        float4 asd = *(const float4*)&g_AS[dtok * 4];

        // self-loop exp term
        float4 eself;
        {
            float vx = asd.x + ad.x, vy = asd.y + ad.y, vz = asd.z + ad.z, vw = asd.w + ad.w;
            vx = vx > 0.f ? vx : 0.2f * vx;
            vy = vy > 0.f ? vy : 0.2f * vy;
            vz = vz > 0.f ? vz : 0.2f * vz;
            vw = vw > 0.f ? vw : 0.2f * vw;
            eself = make_float4(__expf(vx), __expf(vy), __expf(vz), __expf(vw));
        }

        // phase 1: per-edge exp(leaky_relu(logit)) -> smem; partial sums in regs
        float4 sum = make_float4(0.f, 0.f, 0.f, 0.f);
        if (lane == 0) sum = eself;
        int nch = (deg + 31) >> 5;
        for (int c = 0; c < nch; c++) {
            int i = c * 32 + lane;
            if (i < deg) {
                int tok = __ldg(&xg[g_col[rs + i]]);
                float4 as = *(const float4*)&g_AS[tok * 4];
                float vx = as.x + ad.x, vy = as.y + ad.y, vz = as.z + ad.z, vw = as.w + ad.w;
                vx = vx > 0.f ? vx : 0.2f * vx;
                vy = vy > 0.f ? vy : 0.2f * vy;
                vz = vz > 0.f ? vz : 0.2f * vz;
                vw = vw > 0.f ? vw : 0.2f * vw;
                float ex = __expf(vx), ey = __expf(vy), ez = __expf(vz), ew = __expf(vw);
                sum.x += ex; sum.y += ey; sum.z += ez; sum.w += ew;
                if (i < CAP) {
                    float tkf = __int_as_float(tok);
                    s_ent[w][i * 4 + 0] = make_float2(ex, tkf);
                    s_ent[w][i * 4 + 1] = make_float2(ey, tkf);
                    s_ent[w][i * 4 + 2] = make_float2(ez, tkf);
                    s_ent[w][i * 4 + 3] = make_float2(ew, tkf);
                }
            }
        }
        __syncwarp();

        // softmax denominator reduction (per head)
        #pragma unroll
        for (int o = 16; o > 0; o >>= 1) {
            sum.x += __shfl_xor_sync(0xffffffffu, sum.x, o);
            sum.y += __shfl_xor_sync(0xffffffffu, sum.y, o);
            sum.z += __shfl_xor_sync(0xffffffffu, sum.z, o);
            sum.w += __shfl_xor_sync(0xffffffffu, sum.w, o);
        }
        float den = (h == 0) ? sum.x : (h == 1) ? sum.y : (h == 2) ? sum.z : sum.w;
        float inv = 1.f / den;

        // phase 2: gather fp16 HL rows weighted by exp; divide at the end
        float alself = (h == 0) ? eself.x : (h == 1) ? eself.y
                     : (h == 2) ? eself.z : eself.w;
        const uint2* HLv = (const uint2*)g_HLh;
        float4 acc;
        {
            float4 v = h4_to_f4(__ldg(&HLv[(size_t)dtok * 32 + lane]));
            acc = make_float4(alself * v.x, alself * v.y, alself * v.z, alself * v.w);
        }
        int cached = deg < CAP ? deg : CAP;
        const float2* pent = &s_ent[w][h];
        int e = 0;
        for (; e + 3 < cached; e += 4) {
            float2 e0 = pent[(e + 0) * 4];
            float2 e1 = pent[(e + 1) * 4];
            float2 e2 = pent[(e + 2) * 4];
            float2 e3 = pent[(e + 3) * 4];
            uint2 u0 = __ldg(&HLv[(size_t)__float_as_int(e0.y) * 32 + lane]);
            uint2 u1 = __ldg(&HLv[(size_t)__float_as_int(e1.y) * 32 + lane]);
            uint2 u2 = __ldg(&HLv[(size_t)__float_as_int(e2.y) * 32 + lane]);
            uint2 u3 = __ldg(&HLv[(size_t)__float_as_int(e3.y) * 32 + lane]);
            float4 v0 = h4_to_f4(u0), v1 = h4_to_f4(u1);
            float4 v2 = h4_to_f4(u2), v3 = h4_to_f4(u3);
            acc.x = fmaf(e0.x, v0.x, acc.x); acc.y = fmaf(e0.x, v0.y, acc.y);
            acc.z = fmaf(e0.x, v0.z, acc.z); acc.w = fmaf(e0.x, v0.w, acc.w);
            acc.x = fmaf(e1.x, v1.x, acc.x); acc.y = fmaf(e1.x, v1.y, acc.y);
            acc.z = fmaf(e1.x, v1.z, acc.z); acc.w = fmaf(e1.x, v1.w, acc.w);
            acc.x = fmaf(e2.x, v2.x, acc.x); acc.y = fmaf(e2.x, v2.y, acc.y);
            acc.z = fmaf(e2.x, v2.z, acc.z); acc.w = fmaf(e2.x, v2.w, acc.w);
            acc.x = fmaf(e3.x, v3.x, acc.x); acc.y = fmaf(e3.x, v3.y, acc.y);
            acc.z = fmaf(e3.x, v3.z, acc.z); acc.w = fmaf(e3.x, v3.w, acc.w);
        }
        for (; e < cached; e++) {
            float2 e0 = pent[e * 4];
            float4 v = h4_to_f4(__ldg(&HLv[(size_t)__float_as_int(e0.y) * 32 + lane]));
            acc.x = fmaf(e0.x, v.x, acc.x); acc.y = fmaf(e0.x, v.y, acc.y);
            acc.z = fmaf(e0.x, v.z, acc.z); acc.w = fmaf(e0.x, v.w, acc.w);
        }
        if (deg > CAP) {   // rare overflow path
            float adh = (h == 0) ? ad.x : (h == 1) ? ad.y : (h == 2) ? ad.z : ad.w;
            for (e = cached; e < deg; e++) {
                int tok = __ldg(&xg[g_col[rs + e]]);
                float v = g_AS[tok * 4 + h] + adh;
                v = v > 0.f ? v : 0.2f * v;
                float al = __expf(v);
                float4 hv = h4_to_f4(__ldg(&HLv[(size_t)tok * 32 + lane]));
                acc.x = fmaf(al, hv.x, acc.x); acc.y = fmaf(al, hv.y, acc.y);
                acc.z = fmaf(al, hv.z, acc.z); acc.w = fmaf(al, hv.w, acc.w);
            }
        }

        const float4* b4 = (const float4*)bias;
        float4 bb = __ldg(&b4[lane]);
        float4 o4;
        o4.x = acc.x * inv + bb.x;
        o4.y = acc.y * inv + bb.y;
        o4.z = acc.z * inv + bb.z;
        o4.w = acc.w * inv + bb.w;
        ((float4*)out)[(size_t)row * 32 + lane] = o4;
    }

    // last-finishing block resets g_deg for the next graph replay
    __syncthreads();
    if (threadIdx.x == 0) {
        __threadfence();
        s_last = (atomicAdd(&g_done, 1) == (int)gridDim.x - 1);
    }
    __syncthreads();
    if (s_last) {
        for (int i = threadIdx.x; i < N; i += blockDim.x) g_deg[i] = 0;
        if (threadIdx.x == 0) g_done = 0;
    }
}

// ---------------- launch ----------------

extern "C" void kernel_launch(void* const* d_in, const int* in_sizes, int n_in,
                              void* d_out, int out_size) {
    const int*   x       = (const int*)  d_in[0];   // [G*N]
    const int*   adj     = (const int*)  d_in[1];   // [2,E]
    const float* emb     = (const float*)d_in[2];   // [N,32]
    const float* lin_w   = (const float*)d_in[3];   // [32,128]
    const float* att_src = (const float*)d_in[4];   // [128]
    const float* att_dst = (const float*)d_in[5];   // [128]
    const float* bias    = (const float*)d_in[6];   // [128]
    float* out = (float*)d_out;

    int GN = in_sizes[0];
    int E  = in_sizes[1] / 2;
    int N  = in_sizes[2] / EMB;
    int G  = GN / N;

    int SCB = (E + 255) / 256;
    k_fused<<<SCB + TKB, 256>>>(adj, E, emb, lin_w, att_src, att_dst, N, SCB);
    k_agg<<<(GN + WPB - 1) / WPB, WPB * 32>>>(x, bias, out, N, G);
    (void)n_in; (void)out_size;
}